// round 1
// baseline (speedup 1.0000x reference)
#include <cuda_runtime.h>

// Shape: [1, 8, 8, 8, 258, 258, 1] fp32
//   images = 1*8*8*8 = 512, each H=W=258 -> 66564 elems/image
//   total = 34,080,768 elems (divisible by 4; 66564 % 4 == 0 so a 4-vector
//   never crosses an image boundary)
//
// Semantics (all reads from ORIGINAL x; W-axis assigns done last, so W wins
// at corners):
//   if (w == 0)        src = (h, 1)
//   else if (w == 257) src = (h, 256)
//   else if (h == 0)   src = (1, w)
//   else if (h == 257) src = (256, w)
//   else               src = (h, w)
//   out = x[src] * halo[h, w]

#define HW 258
#define IMG_ELEMS (HW * HW)   // 66564
#define TOTAL 34080768

__global__ __launch_bounds__(256)
void set_halo_kernel(const float* __restrict__ x,
                     const float* __restrict__ hm,
                     float* __restrict__ out)
{
    int i4 = blockIdx.x * blockDim.x + threadIdx.x;
    int idx = i4 * 4;
    if (idx >= TOTAL) return;

    int img = idx / IMG_ELEMS;
    int rem = idx - img * IMG_ELEMS;
    int h = rem / HW;
    int w = rem - h * HW;

    const float* __restrict__ xb = x + img * IMG_ELEMS;

    float4 hv = *reinterpret_cast<const float4*>(hm + idx);
    float hvk[4] = {hv.x, hv.y, hv.z, hv.w};
    float r[4];

#pragma unroll
    for (int k = 0; k < 4; ++k) {
        int sh = h, sw = w;
        if (w == 0)            sw = 1;
        else if (w == HW - 1)  sw = HW - 2;
        else if (h == 0)       sh = 1;
        else if (h == HW - 1)  sh = HW - 2;
        r[k] = xb[sh * HW + sw] * hvk[k];
        // advance (h, w) within the image
        if (++w == HW) { w = 0; ++h; }
    }

    *reinterpret_cast<float4*>(out + idx) = make_float4(r[0], r[1], r[2], r[3]);
}

extern "C" void kernel_launch(void* const* d_in, const int* in_sizes, int n_in,
                              void* d_out, int out_size)
{
    const float* x  = (const float*)d_in[0];
    const float* hm = (const float*)d_in[1];
    float* out = (float*)d_out;

    const int n4 = TOTAL / 4;               // 8,520,192
    const int threads = 256;
    const int blocks = (n4 + threads - 1) / threads;  // 33,282
    set_halo_kernel<<<blocks, threads>>>(x, hm, out);
}